// round 3
// baseline (speedup 1.0000x reference)
#include <cuda_runtime.h>
#include <cuda_bf16.h>

// Problem: B=32, N=50000, K=32, E=6, F=3
//   f[b,n,f] = leaky_relu(x[b,n]*s[f] + g[n,f]),  s[f]=sum_e W[f,e], g[n,f]=W[f,:].emb[n,:]+bias[f]
//   out[n,k] = mask * mean_b exp(-||f[b,n,:]-f[b,nbr[n,k],:]||^2)          (2*theta = 1)
//
// Scratch: transposed x (xT[n][b], coalesced 128B row per node) + per-node g packed as float4.

#define NMAX 50000
#define BDIM 32     // batch B (== warp size, load-bearing for the mapping)
#define KDIM 32     // neighbors K (== warp size)

__device__ float  g_xT[NMAX * BDIM];   // 6.4 MB
__device__ float4 g_g4[NMAX];          // 0.8 MB

// ---------------------------------------------------------------------------
// Kernel 1: transpose x (B,N) -> xT (N,B) via smem tile; compute g4[n].
// blockDim = (32, 8). Each block handles 32 nodes.
// ---------------------------------------------------------------------------
__global__ __launch_bounds__(256) void prep_kernel(
    const float* __restrict__ x,      // (B, N)
    const float* __restrict__ emb,    // (N, 6)
    const float* __restrict__ fcw,    // (3, 6)
    const float* __restrict__ fcb,    // (3,)
    int N)
{
    __shared__ float xt[32][33];
    const int n0 = blockIdx.x * 32;
    const int tx = threadIdx.x;
    const int ty = threadIdx.y;

    // Load 32 (b) x 32 (n) tile, coalesced along n.
    #pragma unroll
    for (int i = 0; i < 4; i++) {
        int b = ty + 8 * i;
        int n = n0 + tx;
        xt[b][tx] = (n < N) ? x[b * N + n] : 0.0f;
    }
    __syncthreads();

    // Store transposed: xT[n][b], coalesced along b.
    #pragma unroll
    for (int i = 0; i < 4; i++) {
        int r = ty + 8 * i;      // node index within tile
        int n = n0 + r;
        if (n < N) g_xT[n * BDIM + tx] = xt[tx][r];
    }

    // g4[n] = (W . emb[n] + bias), one thread per node (first warp only).
    const int tid = ty * 32 + tx;
    if (tid < 32) {
        int n = n0 + tid;
        if (n < N) {
            float e0 = emb[n * 6 + 0], e1 = emb[n * 6 + 1], e2 = emb[n * 6 + 2];
            float e3 = emb[n * 6 + 3], e4 = emb[n * 6 + 4], e5 = emb[n * 6 + 5];
            float g[3];
            #pragma unroll
            for (int f = 0; f < 3; f++) {
                g[f] = fcb[f]
                     + fcw[f * 6 + 0] * e0 + fcw[f * 6 + 1] * e1
                     + fcw[f * 6 + 2] * e2 + fcw[f * 6 + 3] * e3
                     + fcw[f * 6 + 4] * e4 + fcw[f * 6 + 5] * e5;
            }
            g_g4[n] = make_float4(g[0], g[1], g[2], 0.0f);
        }
    }
}

// ---------------------------------------------------------------------------
// Kernel 2: one warp per node.
//   Phase 1 (lane = b): stage neighbor x-rows into smem xs[b][k] (pad 33 ->
//     conflict-free for both the [lane][k] store and the [b][lane] read),
//     self f into broadcastable float4 table, neighbor g4 into registers.
//   Phase 2 (lane = k): serial b-loop, recompute neighbor f on the fly,
//     accumulate exp(-d) in a register. One coalesced store per node.
// ---------------------------------------------------------------------------
__global__ __launch_bounds__(256) void pair_kernel(
    const int*  __restrict__ nl,      // (N, 32)
    const float* __restrict__ fcw,    // (3, 6)
    float* __restrict__ out,          // (N, 32)
    int N)
{
    __shared__ float  xs[8][32 * 33];   // per-warp staged neighbor x rows
    __shared__ float4 fs4[8][32];       // per-warp self f (indexed by b)

    const int wid  = threadIdx.x >> 5;
    const int lane = threadIdx.x & 31;
    const int n    = blockIdx.x * 8 + wid;
    if (n >= N) return;

    // s[f] = sum_e W[f,e]  (uniform, cheap)
    float s0 = 0.f, s1 = 0.f, s2 = 0.f;
    #pragma unroll
    for (int e = 0; e < 6; e++) {
        s0 += fcw[e];
        s1 += fcw[6 + e];
        s2 += fcw[12 + e];
    }

    // --- Phase 1: lane = b ---
    // Self f for this (b = lane).
    {
        float xv = g_xT[n * BDIM + lane];
        float4 gs = g_g4[n];
        float t0 = fmaf(xv, s0, gs.x);
        float t1 = fmaf(xv, s1, gs.y);
        float t2 = fmaf(xv, s2, gs.z);
        fs4[wid][lane] = make_float4(fmaxf(t0, 0.2f * t0),
                                     fmaxf(t1, 0.2f * t1),
                                     fmaxf(t2, 0.2f * t2), 0.0f);
    }

    // This lane's neighbor (for phase 2, lane = k).
    const int   j    = nl[n * KDIM + lane];
    const int   jc   = (j < 0) ? 0 : j;
    const float mask = (j < 0) ? 0.0f : 1.0f;
    const float4 gj  = g_g4[jc];

    // Stage all 32 neighbor x-rows: xs[b = lane][k], coalesced 128B gathers.
    #pragma unroll 4
    for (int k = 0; k < KDIM; k++) {
        int jj = __shfl_sync(0xffffffffu, jc, k);
        xs[wid][lane * 33 + k] = g_xT[jj * BDIM + lane];
    }
    __syncwarp();

    // --- Phase 2: lane = k ---
    float acc = 0.0f;
    #pragma unroll 8
    for (int b = 0; b < BDIM; b++) {
        float  xv = xs[wid][b * 33 + lane];   // neighbor's x[b]
        float4 fs = fs4[wid][b];              // self f[b][:], broadcast
        float u0 = fmaf(xv, s0, gj.x);
        float u1 = fmaf(xv, s1, gj.y);
        float u2 = fmaf(xv, s2, gj.z);
        float fn0 = fmaxf(u0, 0.2f * u0);
        float fn1 = fmaxf(u1, 0.2f * u1);
        float fn2 = fmaxf(u2, 0.2f * u2);
        float d0 = fs.x - fn0;
        float d1 = fs.y - fn1;
        float d2 = fs.z - fn2;
        float d  = fmaf(d2, d2, fmaf(d1, d1, d0 * d0));
        acc += __expf(-d);
    }

    out[n * KDIM + lane] = acc * (1.0f / 32.0f) * mask;
}

// ---------------------------------------------------------------------------
extern "C" void kernel_launch(void* const* d_in, const int* in_sizes, int n_in,
                              void* d_out, int out_size)
{
    const float* x    = (const float*)d_in[0];   // (B, N)
    const float* emb  = (const float*)d_in[1];   // (N, 6)
    const float* fcw  = (const float*)d_in[2];   // (3, 6)
    const float* fcb  = (const float*)d_in[3];   // (3,)
    const int*   nl   = (const int*)d_in[4];     // (N, 32)
    float*       out  = (float*)d_out;           // (N, 32)

    const int N = in_sizes[1] / 6;               // 50000

    dim3 b1(32, 8);
    prep_kernel<<<(N + 31) / 32, b1>>>(x, emb, fcw, fcb, N);

    pair_kernel<<<(N + 7) / 8, 256>>>(nl, fcw, out, N);
}

// round 4
// speedup vs baseline: 1.1472x; 1.1472x over previous
#include <cuda_runtime.h>
#include <cuda_bf16.h>

// Problem: B=32, N=50000, K=32, E=6, F=3
//   f[b,n,f] = leaky_relu(x[b,n]*s[f] + g[n,f]),  s[f]=sum_e W[f,e], g[n,f]=W[f,:].emb[n,:]+bias[f]
//   out[n,k] = mask * mean_b exp(-||f[b,n,:]-f[b,nbr[n,k],:]||^2)          (2*theta = 1)
//
// Identities used:
//   lrelu(u) = 0.6u + 0.4|u|   (slope 0.2), positively homogeneous =>
//   pre-scaling s,g by c = sqrt(log2 e) makes sum(d^2) log2-scaled, so
//   exp(-d) = ex2(-(d0^2+d1^2+d2^2)) with the neg folded into FFMA modifiers.

#define NMAX 50000
#define BDIM 32
#define KDIM 32
#define XPAD 36                       // row pad: 36 = 4 (mod 32) -> conflict-free
#define C_SCALE 1.2011224087864498f   // sqrt(log2(e))

__device__ float  g_xT[NMAX * BDIM];   // 6.4 MB, transposed x
__device__ float4 g_g4[NMAX];          // 0.8 MB, pre-scaled g

// ---------------------------------------------------------------------------
// Kernel 1: transpose x (B,N) -> xT (N,B); compute scaled g4[n].
// ---------------------------------------------------------------------------
__global__ __launch_bounds__(256) void prep_kernel(
    const float* __restrict__ x,      // (B, N)
    const float* __restrict__ emb,    // (N, 6)
    const float* __restrict__ fcw,    // (3, 6)
    const float* __restrict__ fcb,    // (3,)
    int N)
{
    __shared__ float xt[32][33];
    const int n0 = blockIdx.x * 32;
    const int tx = threadIdx.x;
    const int ty = threadIdx.y;

    #pragma unroll
    for (int i = 0; i < 4; i++) {
        int b = ty + 8 * i;
        int n = n0 + tx;
        xt[b][tx] = (n < N) ? x[b * N + n] : 0.0f;
    }
    __syncthreads();

    #pragma unroll
    for (int i = 0; i < 4; i++) {
        int r = ty + 8 * i;
        int n = n0 + r;
        if (n < N) g_xT[n * BDIM + tx] = xt[tx][r];
    }

    const int tid = ty * 32 + tx;
    if (tid < 32) {
        int n = n0 + tid;
        if (n < N) {
            float e0 = emb[n * 6 + 0], e1 = emb[n * 6 + 1], e2 = emb[n * 6 + 2];
            float e3 = emb[n * 6 + 3], e4 = emb[n * 6 + 4], e5 = emb[n * 6 + 5];
            float g[3];
            #pragma unroll
            for (int f = 0; f < 3; f++) {
                g[f] = fcb[f]
                     + fcw[f * 6 + 0] * e0 + fcw[f * 6 + 1] * e1
                     + fcw[f * 6 + 2] * e2 + fcw[f * 6 + 3] * e3
                     + fcw[f * 6 + 4] * e4 + fcw[f * 6 + 5] * e5;
            }
            g_g4[n] = make_float4(C_SCALE * g[0], C_SCALE * g[1],
                                  C_SCALE * g[2], 0.0f);
        }
    }
}

// ---------------------------------------------------------------------------
// Kernel 2: one warp per node.
//   Phase 1 (lane = b): stage neighbor x-rows as xs[k][b] (pad 36), self-f as
//     SoA fs0/fs1/fs2[b].
//   Phase 2 (lane = k): loop b in groups of 4; vector LDS of xv4 + broadcast
//     LDS of fs; leaky-relu distance via FFMA-imm forms; bare ex2.approx.
// ---------------------------------------------------------------------------
__global__ __launch_bounds__(256, 5) void pair_kernel(
    const int*  __restrict__ nl,      // (N, 32)
    const float* __restrict__ fcw,    // (3, 6)
    float* __restrict__ out,          // (N, 32)
    int N)
{
    __shared__ float xs[8][KDIM * XPAD];   // per-warp neighbor x rows, [k][b]
    __shared__ float fs0[8][32], fs1[8][32], fs2[8][32];

    const int wid  = threadIdx.x >> 5;
    const int lane = threadIdx.x & 31;
    const int n    = blockIdx.x * 8 + wid;
    if (n >= N) return;

    // scaled s[f] = C * sum_e W[f,e]
    float s0 = 0.f, s1 = 0.f, s2 = 0.f;
    #pragma unroll
    for (int e = 0; e < 6; e++) {
        s0 += fcw[e];
        s1 += fcw[6 + e];
        s2 += fcw[12 + e];
    }
    s0 *= C_SCALE; s1 *= C_SCALE; s2 *= C_SCALE;

    // --- Phase 1: lane = b ---
    {
        float  xv = g_xT[n * BDIM + lane];
        float4 gs = g_g4[n];
        float u0 = fmaf(xv, s0, gs.x);
        float u1 = fmaf(xv, s1, gs.y);
        float u2 = fmaf(xv, s2, gs.z);
        fs0[wid][lane] = fmaf(0.4f, fabsf(u0), 0.6f * u0);
        fs1[wid][lane] = fmaf(0.4f, fabsf(u1), 0.6f * u1);
        fs2[wid][lane] = fmaf(0.4f, fabsf(u2), 0.6f * u2);
    }

    const int   j    = nl[n * KDIM + lane];
    const int   jc   = (j < 0) ? 0 : j;
    const float mask = (j < 0) ? 0.0f : 1.0f;
    const float4 gj  = g_g4[jc];

    // Stage neighbor x rows: xs[k][b = lane]. Store banks (4k+lane)%32: clean.
    #pragma unroll 4
    for (int k = 0; k < KDIM; k++) {
        int jj = __shfl_sync(0xffffffffu, jc, k);
        xs[wid][k * XPAD + lane] = g_xT[jj * BDIM + lane];
    }
    __syncwarp();

    // --- Phase 2: lane = k ---
    const float* xrow = &xs[wid][lane * XPAD];
    float acc0 = 0.0f, acc1 = 0.0f;

    #pragma unroll
    for (int g = 0; g < 8; g++) {
        float4 xv4  = *(const float4*)(xrow + g * 4);
        float4 f0v  = *(const float4*)&fs0[wid][g * 4];
        float4 f1v  = *(const float4*)&fs1[wid][g * 4];
        float4 f2v  = *(const float4*)&fs2[wid][g * 4];

        #define PAIR_STEP(XV, F0, F1, F2, ACC)                                \
        {                                                                     \
            float u0 = fmaf((XV), s0, gj.x);                                  \
            float u1 = fmaf((XV), s1, gj.y);                                  \
            float u2 = fmaf((XV), s2, gj.z);                                  \
            float d0 = fmaf(u0, -0.6f, (F0)); d0 = fmaf(fabsf(u0), -0.4f, d0);\
            float d1 = fmaf(u1, -0.6f, (F1)); d1 = fmaf(fabsf(u1), -0.4f, d1);\
            float d2 = fmaf(u2, -0.6f, (F2)); d2 = fmaf(fabsf(u2), -0.4f, d2);\
            float dn = -d0 * d0;                                              \
            dn = fmaf(d1, -d1, dn);                                           \
            dn = fmaf(d2, -d2, dn);                                           \
            float ex;                                                         \
            asm("ex2.approx.ftz.f32 %0, %1;" : "=f"(ex) : "f"(dn));           \
            (ACC) += ex;                                                      \
        }

        PAIR_STEP(xv4.x, f0v.x, f1v.x, f2v.x, acc0)
        PAIR_STEP(xv4.y, f0v.y, f1v.y, f2v.y, acc1)
        PAIR_STEP(xv4.z, f0v.z, f1v.z, f2v.z, acc0)
        PAIR_STEP(xv4.w, f0v.w, f1v.w, f2v.w, acc1)
        #undef PAIR_STEP
    }

    out[n * KDIM + lane] = (acc0 + acc1) * (1.0f / 32.0f) * mask;
}

// ---------------------------------------------------------------------------
extern "C" void kernel_launch(void* const* d_in, const int* in_sizes, int n_in,
                              void* d_out, int out_size)
{
    const float* x    = (const float*)d_in[0];   // (B, N)
    const float* emb  = (const float*)d_in[1];   // (N, 6)
    const float* fcw  = (const float*)d_in[2];   // (3, 6)
    const float* fcb  = (const float*)d_in[3];   // (3,)
    const int*   nl   = (const int*)d_in[4];     // (N, 32)
    float*       out  = (float*)d_out;           // (N, 32)

    const int N = in_sizes[1] / 6;               // 50000

    dim3 b1(32, 8);
    prep_kernel<<<(N + 31) / 32, b1>>>(x, emb, fcw, fcb, N);

    pair_kernel<<<(N + 7) / 8, 256>>>(nl, fcw, out, N);
}